// round 6
// baseline (speedup 1.0000x reference)
#include <cuda_runtime.h>
#include <cfloat>
#include <cstdint>

// ---------------------------------------------------------------------------
// Static scratch (no cudaMalloc allowed). Two ping-pong buffers sized for the
// largest tensor: 128*128*32 voxels * 64 ch = 33,554,432 floats (128 MiB each).
// ---------------------------------------------------------------------------
__device__ float g_bufA[33554432];
__device__ float g_bufB[33554432];
__device__ float g_m0[524288];   // 128*128*32
__device__ float g_m1[65536];    // 64*64*16
__device__ float g_m2[8192];     // 32*32*8
__device__ float g_m3[1024];     // 16*16*4
__device__ float g_m4[128];      // 8*8*2
__device__ float g_m5[16];       // 4*4*1

// ---------------------------------------------------------------------------
// Scatter points into dense grid (grid is pre-zeroed with memset)
// ---------------------------------------------------------------------------
__global__ void scatter_kernel(const float* __restrict__ feats,
                               const int* __restrict__ coors, int n,
                               float* __restrict__ x0, float* __restrict__ m0)
{
    int i = blockIdx.x * blockDim.x + threadIdx.x;
    if (i >= n) return;
    int z = coors[i * 4 + 1], y = coors[i * 4 + 2], xw = coors[i * 4 + 3];
    int v = (z * 128 + y) * 32 + xw;
    m0[v] = 1.0f;
    x0[v * 3 + 0] = feats[i * 3 + 0];
    x0[v * 3 + 1] = feats[i * 3 + 1];
    x0[v * 3 + 2] = feats[i * 3 + 2];
}

// ---------------------------------------------------------------------------
// Submanifold conv at full resolution: compute ONLY at the N active sites
// taken from the coors list (3x3x3, stride 1, pad 1). Output buffer must be
// zeroed beforehand so inactive voxels read 0 in the next layer.
// blockDim.x == COUT. Each block handles NS sites.
// ---------------------------------------------------------------------------
template <int CIN, int COUT, int NS>
__global__ void conv_subm(const float* __restrict__ in,
                          const float* __restrict__ wgt,
                          float* __restrict__ out,
                          const int* __restrict__ coors, int nsites,
                          int D, int H, int W)
{
    constexpr int CCH = (CIN % 32 == 0) ? 32 : CIN;
    const int tid = threadIdx.x;
    const int base = blockIdx.x * NS;

    __shared__ int sz[NS], sy[NS], sx[NS];
    __shared__ float xs[NS][CCH + 1];

    if (tid < NS) {
        int i = base + tid;
        if (i < nsites) {
            sz[tid] = coors[i * 4 + 1] - 1;
            sy[tid] = coors[i * 4 + 2] - 1;
            sx[tid] = coors[i * 4 + 3] - 1;
        } else {
            sz[tid] = -100000; sy[tid] = 0; sx[tid] = 0;
        }
    }
    __syncthreads();

    float acc[NS];
#pragma unroll
    for (int s = 0; s < NS; s++) acc[s] = 0.f;

    for (int tap = 0; tap < 27; tap++) {
        const int dz = tap / 9, dy = (tap / 3) % 3, dx = tap % 3;
        for (int ci0 = 0; ci0 < CIN; ci0 += CCH) {
            for (int e = tid; e < NS * CCH; e += COUT) {
                int s = e / CCH, ci = e - s * CCH;
                int iz = sz[s] + dz, iy = sy[s] + dy, ix = sx[s] + dx;
                float v = 0.f;
                if ((unsigned)iz < (unsigned)D && (unsigned)iy < (unsigned)H &&
                    (unsigned)ix < (unsigned)W)
                    v = in[(size_t)((iz * H + iy) * W + ix) * CIN + ci0 + ci];
                xs[s][ci] = v;
            }
            __syncthreads();
            const float* wp = wgt + (size_t)(tap * CIN + ci0) * COUT + tid;
#pragma unroll 4
            for (int ci = 0; ci < CCH; ci++) {
                float wv = __ldg(wp + (size_t)ci * COUT);
#pragma unroll
                for (int s = 0; s < NS; s++) acc[s] += xs[s][ci] * wv;
            }
            __syncthreads();
        }
    }

#pragma unroll
    for (int s = 0; s < NS; s++) {
        int i = base + s;
        if (i < nsites) {
            int v = ((sz[s] + 1) * H + (sy[s] + 1)) * W + (sx[s] + 1);
            out[(size_t)v * COUT + tid] = acc[s];
        }
    }
}

// ---------------------------------------------------------------------------
// Dense 3D conv, optional mask epilogue (out *= mask[o]).
// blockDim.x == COUT. Each block handles NS output sites.
// ---------------------------------------------------------------------------
template <int CIN, int COUT, int K, int STRIDE, int NS>
__global__ void conv_dense(const float* __restrict__ in,
                           const float* __restrict__ wgt,
                           float* __restrict__ out,
                           const float* __restrict__ mask,
                           int Din, int Hin, int Win,
                           int Dout, int Hout, int Wout, int pad)
{
    constexpr int CCH = (CIN % 32 == 0) ? 32 : CIN;
    const int tid = threadIdx.x;
    const int nout = Dout * Hout * Wout;
    const int base = blockIdx.x * NS;

    __shared__ int sz[NS], sy[NS], sx[NS];
    __shared__ float xs[NS][CCH + 1];

    if (tid < NS) {
        int o = base + tid;
        if (o < nout) {
            int xw = o % Wout, yy = (o / Wout) % Hout, zz = o / (Wout * Hout);
            sz[tid] = zz * STRIDE - pad;
            sy[tid] = yy * STRIDE - pad;
            sx[tid] = xw * STRIDE - pad;
        } else {
            sz[tid] = -100000; sy[tid] = 0; sx[tid] = 0;
        }
    }
    __syncthreads();

    float acc[NS];
#pragma unroll
    for (int s = 0; s < NS; s++) acc[s] = 0.f;

    for (int tap = 0; tap < K * K * K; tap++) {
        const int dz = tap / (K * K), dy = (tap / K) % K, dx = tap % K;
        for (int ci0 = 0; ci0 < CIN; ci0 += CCH) {
            for (int e = tid; e < NS * CCH; e += COUT) {
                int s = e / CCH, ci = e - s * CCH;
                int iz = sz[s] + dz, iy = sy[s] + dy, ix = sx[s] + dx;
                float v = 0.f;
                if ((unsigned)iz < (unsigned)Din && (unsigned)iy < (unsigned)Hin &&
                    (unsigned)ix < (unsigned)Win)
                    v = in[(size_t)((iz * Hin + iy) * Win + ix) * CIN + ci0 + ci];
                xs[s][ci] = v;
            }
            __syncthreads();
            const float* wp = wgt + (size_t)(tap * CIN + ci0) * COUT + tid;
#pragma unroll 4
            for (int ci = 0; ci < CCH; ci++) {
                float wv = __ldg(wp + (size_t)ci * COUT);
#pragma unroll
                for (int s = 0; s < NS; s++) acc[s] += xs[s][ci] * wv;
            }
            __syncthreads();
        }
    }

#pragma unroll
    for (int s = 0; s < NS; s++) {
        int o = base + s;
        if (o < nout) {
            float mv = mask ? mask[o] : 1.f;
            out[(size_t)o * COUT + tid] = acc[s] * mv;
        }
    }
}

// ---------------------------------------------------------------------------
// Mask pool: reduce_window(max) with init 0
// ---------------------------------------------------------------------------
__global__ void mask_pool_kernel(const float* __restrict__ m, float* __restrict__ mo,
                                 int Din, int Hin, int Win,
                                 int Dout, int Hout, int Wout,
                                 int k, int s, int pad)
{
    int o = blockIdx.x * blockDim.x + threadIdx.x;
    int nout = Dout * Hout * Wout;
    if (o >= nout) return;
    int xw = o % Wout, y = (o / Wout) % Hout, z = o / (Wout * Hout);
    float r = 0.f;
    for (int dz = 0; dz < k; dz++)
        for (int dy = 0; dy < k; dy++)
            for (int dx = 0; dx < k; dx++) {
                int iz = z * s - pad + dz, iy = y * s - pad + dy, ix = xw * s - pad + dx;
                if ((unsigned)iz < (unsigned)Din && (unsigned)iy < (unsigned)Hin &&
                    (unsigned)ix < (unsigned)Win)
                    r = fmaxf(r, m[(iz * Hin + iy) * Win + ix]);
            }
    mo[o] = r;
}

// ---------------------------------------------------------------------------
// Masked max pool 2x2x2 stride 2 VALID. Writes pooled x and pooled mask.
// blockDim.x == C, gridDim.x == nout.
// ---------------------------------------------------------------------------
template <int C>
__global__ void maxpool_kernel(const float* __restrict__ x, const float* __restrict__ m,
                               float* __restrict__ xo, float* __restrict__ mo,
                               int Hin, int Win, int Hout, int Wout)
{
    int o = blockIdx.x;
    int c = threadIdx.x;
    int xw = o % Wout, y = (o / Wout) % Hout, z = o / (Wout * Hout);
    float best = -FLT_MAX, mn = 0.f;
    for (int dz = 0; dz < 2; dz++)
        for (int dy = 0; dy < 2; dy++)
            for (int dx = 0; dx < 2; dx++) {
                int v = ((2 * z + dz) * Hin + (2 * y + dy)) * Win + (2 * xw + dx);
                float mv = m[v];
                mn = fmaxf(mn, mv);
                float xv = x[(size_t)v * C + c];
                best = fmaxf(best, mv > 0.f ? xv : -FLT_MAX);
            }
    xo[(size_t)o * C + c] = (mn > 0.f) ? best : 0.f;
    if (c == 0) mo[o] = mn;
}

// ---------------------------------------------------------------------------
// conv_transpose k=2 s=2 VALID (JAX transpose_kernel=False):
//   out[z,y,x,co] = sum_ci in[z/2,y/2,x/2,ci] * w[1-z%2, 1-y%2, 1-x%2, ci, co]
// then multiplied by mask. blockDim.x == COUT, gridDim.x == nout.
// ---------------------------------------------------------------------------
template <int CIN, int COUT>
__global__ void deconv_kernel(const float* __restrict__ in,
                              const float* __restrict__ wgt,
                              float* __restrict__ out,
                              const float* __restrict__ mask,
                              int Hout, int Wout)
{
    int o = blockIdx.x;
    int c = threadIdx.x;
    int xw = o % Wout, y = (o / Wout) % Hout, z = o / (Wout * Hout);
    int Hin = Hout / 2, Win = Wout / 2;
    int iv = ((z / 2) * Hin + (y / 2)) * Win + (xw / 2);
    int tap = ((1 - (z & 1)) * 2 + (1 - (y & 1))) * 2 + (1 - (xw & 1));
    const float* wp = wgt + (size_t)tap * CIN * COUT + c;
    const float* ip = in + (size_t)iv * CIN;
    float acc = 0.f;
#pragma unroll 4
    for (int ci = 0; ci < CIN; ci++)
        acc += ip[ci] * __ldg(wp + (size_t)ci * COUT);
    out[(size_t)o * COUT + c] = acc * mask[o];
}

// ---------------------------------------------------------------------------
// Host launcher
// ---------------------------------------------------------------------------
extern "C" void kernel_launch(void* const* d_in, const int* in_sizes, int n_in,
                              void* d_out, int out_size)
{
    const float* feats = (const float*)d_in[0];
    const int*   coors = (const int*)d_in[1];
    const float* w[19];
    for (int i = 1; i <= 18; i++) w[i] = (const float*)d_in[2 + i];
    float* out = (float*)d_out;
    const int N = in_sizes[0] / 3;

    float *A, *B, *m0, *m1, *m2, *m3, *m4, *m5;
    cudaGetSymbolAddress((void**)&A,  g_bufA);
    cudaGetSymbolAddress((void**)&B,  g_bufB);
    cudaGetSymbolAddress((void**)&m0, g_m0);
    cudaGetSymbolAddress((void**)&m1, g_m1);
    cudaGetSymbolAddress((void**)&m2, g_m2);
    cudaGetSymbolAddress((void**)&m3, g_m3);
    cudaGetSymbolAddress((void**)&m4, g_m4);
    cudaGetSymbolAddress((void**)&m5, g_m5);

    const int nv0 = 128 * 128 * 32;   // 524288
    const int nv1 = 64 * 64 * 16;     // 65536
    const int nv2 = 32 * 32 * 8;      // 8192
    const int nv3 = 16 * 16 * 4;      // 1024
    const int nv4 = 8 * 8 * 2;        // 128
    const int nv5 = 4 * 4 * 1;        // 16

    // ---- scatter: x0 (bufA, 3ch) + m0 ----
    cudaMemsetAsync(m0, 0, (size_t)nv0 * 4, 0);
    cudaMemsetAsync(A,  0, (size_t)nv0 * 3 * 4, 0);
    scatter_kernel<<<(N + 255) / 256, 256>>>(feats, coors, N, A, m0);

    const int gsub = (N + 31) / 32;
    // ---- w1: subm 3->32, A->B ----
    cudaMemsetAsync(B, 0, (size_t)nv0 * 32 * 4, 0);
    conv_subm<3, 32, 32><<<gsub, 32>>>(A, w[1], B, coors, N, 128, 128, 32);
    // ---- w2: subm 32->32, B->A ----
    cudaMemsetAsync(A, 0, (size_t)nv0 * 32 * 4, 0);
    conv_subm<32, 32, 32><<<gsub, 32>>>(B, w[2], A, coors, N, 128, 128, 32);
    // ---- w3: subm 32->64, A->B ----
    cudaMemsetAsync(B, 0, (size_t)nv0 * 64 * 4, 0);
    conv_subm<32, 64, 32><<<gsub, 64>>>(A, w[3], B, coors, N, 128, 128, 32);
    // ---- w4: subm 64->64, B->A ----
    cudaMemsetAsync(A, 0, (size_t)nv0 * 64 * 4, 0);
    conv_subm<64, 64, 32><<<gsub, 64>>>(B, w[4], A, coors, N, 128, 128, 32);

    // ---- m1 = mask_pool(m0, 3, 2, pad 1) ----
    mask_pool_kernel<<<(nv1 + 255) / 256, 256>>>(m0, m1, 128, 128, 32, 64, 64, 16, 3, 2, 1);
    // ---- w5: conv 64->64 k3 s2 pad1, A->B, *m1 ----
    conv_dense<64, 64, 3, 2, 32><<<nv1 / 32, 64>>>(A, w[5], B, m1, 128, 128, 32, 64, 64, 16, 1);
    // ---- w6: subm(dense) 64->96, B->A, *m1 ----
    conv_dense<64, 96, 3, 1, 32><<<nv1 / 32, 96>>>(B, w[6], A, m1, 64, 64, 16, 64, 64, 16, 1);
    // ---- w7: 96->96, A->B, *m1 ----
    conv_dense<96, 96, 3, 1, 32><<<nv1 / 32, 96>>>(A, w[7], B, m1, 64, 64, 16, 64, 64, 16, 1);

    // ---- m2 = mask_pool(m1, 2, 2, VALID) ----
    mask_pool_kernel<<<(nv2 + 255) / 256, 256>>>(m1, m2, 64, 64, 16, 32, 32, 8, 2, 2, 0);
    // ---- w8: conv 96->96 k2 s2 VALID, B->A, *m2 ----
    conv_dense<96, 96, 2, 2, 32><<<nv2 / 32, 96>>>(B, w[8], A, m2, 64, 64, 16, 32, 32, 8, 0);
    // ---- w9: 96->128, A->B, *m2 ----
    conv_dense<96, 128, 3, 1, 16><<<nv2 / 16, 128>>>(A, w[9], B, m2, 32, 32, 8, 32, 32, 8, 1);
    // ---- w10: 128->128, B->A, *m2 ----
    conv_dense<128, 128, 3, 1, 16><<<nv2 / 16, 128>>>(B, w[10], A, m2, 32, 32, 8, 32, 32, 8, 1);

    // ---- maxpool S2->S3 : (A, m2) -> (B, m3) ----
    maxpool_kernel<128><<<nv3, 128>>>(A, m2, B, m3, 32, 8, 16, 4);
    // ---- w11: 128->160, B->A, *m3 ----
    conv_dense<128, 160, 3, 1, 8><<<nv3 / 8, 160>>>(B, w[11], A, m3, 16, 16, 4, 16, 16, 4, 1);
    // ---- w12: 160->160, A->B, *m3 ----
    conv_dense<160, 160, 3, 1, 8><<<nv3 / 8, 160>>>(A, w[12], B, m3, 16, 16, 4, 16, 16, 4, 1);

    // ---- maxpool S3->S4 : (B, m3) -> (A, m4) ----
    maxpool_kernel<160><<<nv4, 160>>>(B, m3, A, m4, 16, 4, 8, 2);
    // ---- w13: 160->192, A->B, *m4 ----
    conv_dense<160, 192, 3, 1, 1><<<nv4, 192>>>(A, w[13], B, m4, 8, 8, 2, 8, 8, 2, 1);
    // ---- w14: 192->192, B->A, *m4 ----
    conv_dense<192, 192, 3, 1, 1><<<nv4, 192>>>(B, w[14], A, m4, 8, 8, 2, 8, 8, 2, 1);

    // ---- maxpool S4->S5 : (A, m4) -> (B, m5) ----
    maxpool_kernel<192><<<nv5, 192>>>(A, m4, B, m5, 8, 2, 4, 1);
    // ---- w15: 192->224, B->A, *m5 ----
    conv_dense<192, 224, 3, 1, 1><<<nv5, 224>>>(B, w[15], A, m5, 4, 4, 1, 4, 4, 1, 1);
    // ---- w16: 224->224, A->B, *m5 ----
    conv_dense<224, 224, 3, 1, 1><<<nv5, 224>>>(A, w[16], B, m5, 4, 4, 1, 4, 4, 1, 1);

    // ---- deconv w17: 224->128, S5 -> S4, *m4 : B->A ----
    deconv_kernel<224, 128><<<nv4, 128>>>(B, w[17], A, m4, 8, 2);
    // ---- deconv w18: 128->64, S4 -> S3, *m3 : A -> d_out ----
    deconv_kernel<128, 64><<<nv3, 64>>>(A, w[18], out, m3, 16, 4);

    (void)n_in; (void)out_size; (void)m5;
}

// round 7
// speedup vs baseline: 1.4332x; 1.4332x over previous
#include <cuda_runtime.h>
#include <cfloat>
#include <cstdint>

// ---------------------------------------------------------------------------
// Static scratch (no cudaMalloc allowed). Two ping-pong buffers sized for the
// largest tensor: 128*128*32 voxels * 64 ch = 33,554,432 floats (128 MiB each).
// ---------------------------------------------------------------------------
__device__ float g_bufA[33554432];
__device__ float g_bufB[33554432];
__device__ float g_m0[524288];   // 128*128*32
__device__ float g_m1[65536];    // 64*64*16
__device__ float g_m2[8192];     // 32*32*8
__device__ float g_m3[1024];     // 16*16*4
__device__ float g_m4[128];      // 8*8*2
__device__ float g_m5[16];       // 4*4*1

// ---------------------------------------------------------------------------
// Scatter points into dense grid (grid is pre-zeroed with memset)
// ---------------------------------------------------------------------------
__global__ void scatter_kernel(const float* __restrict__ feats,
                               const int* __restrict__ coors, int n,
                               float* __restrict__ x0, float* __restrict__ m0)
{
    int i = blockIdx.x * blockDim.x + threadIdx.x;
    if (i >= n) return;
    int z = coors[i * 4 + 1], y = coors[i * 4 + 2], xw = coors[i * 4 + 3];
    int v = (z * 128 + y) * 32 + xw;
    m0[v] = 1.0f;
    x0[v * 3 + 0] = feats[i * 3 + 0];
    x0[v * 3 + 1] = feats[i * 3 + 1];
    x0[v * 3 + 2] = feats[i * 3 + 2];
}

// ---------------------------------------------------------------------------
// Submanifold conv at full resolution: compute ONLY at the N active sites
// taken from the coors list (3x3x3, stride 1, pad 1). Output buffer must be
// zeroed beforehand so inactive voxels read 0 in the next layer.
// blockDim.x == COUT. Each block handles NS sites.
// ---------------------------------------------------------------------------
template <int CIN, int COUT, int NS>
__global__ void conv_subm(const float* __restrict__ in,
                          const float* __restrict__ wgt,
                          float* __restrict__ out,
                          const int* __restrict__ coors, int nsites,
                          int D, int H, int W)
{
    constexpr int CCH = (CIN % 32 == 0) ? 32 : CIN;
    const int tid = threadIdx.x;
    const int base = blockIdx.x * NS;

    __shared__ int sz[NS], sy[NS], sx[NS];
    __shared__ float xs[NS][CCH + 1];

    if (tid < NS) {
        int i = base + tid;
        if (i < nsites) {
            sz[tid] = coors[i * 4 + 1] - 1;
            sy[tid] = coors[i * 4 + 2] - 1;
            sx[tid] = coors[i * 4 + 3] - 1;
        } else {
            sz[tid] = -100000; sy[tid] = 0; sx[tid] = 0;
        }
    }
    __syncthreads();

    float acc[NS];
#pragma unroll
    for (int s = 0; s < NS; s++) acc[s] = 0.f;

    for (int tap = 0; tap < 27; tap++) {
        const int dz = tap / 9, dy = (tap / 3) % 3, dx = tap % 3;
        for (int ci0 = 0; ci0 < CIN; ci0 += CCH) {
            for (int e = tid; e < NS * CCH; e += COUT) {
                int s = e / CCH, ci = e - s * CCH;
                int iz = sz[s] + dz, iy = sy[s] + dy, ix = sx[s] + dx;
                float v = 0.f;
                if ((unsigned)iz < (unsigned)D && (unsigned)iy < (unsigned)H &&
                    (unsigned)ix < (unsigned)W)
                    v = in[(size_t)((iz * H + iy) * W + ix) * CIN + ci0 + ci];
                xs[s][ci] = v;
            }
            __syncthreads();
            const float* wp = wgt + (size_t)(tap * CIN + ci0) * COUT + tid;
#pragma unroll 4
            for (int ci = 0; ci < CCH; ci++) {
                float wv = __ldg(wp + (size_t)ci * COUT);
#pragma unroll
                for (int s = 0; s < NS; s++) acc[s] += xs[s][ci] * wv;
            }
            __syncthreads();
        }
    }

#pragma unroll
    for (int s = 0; s < NS; s++) {
        int i = base + s;
        if (i < nsites) {
            int v = ((sz[s] + 1) * H + (sy[s] + 1)) * W + (sx[s] + 1);
            out[(size_t)v * COUT + tid] = acc[s];
        }
    }
}

// ---------------------------------------------------------------------------
// Dense 3D conv, optional mask epilogue (out *= mask[o]).
// blockDim.x == COUT. Each block handles NS output sites.
// ---------------------------------------------------------------------------
template <int CIN, int COUT, int K, int STRIDE, int NS>
__global__ void conv_dense(const float* __restrict__ in,
                           const float* __restrict__ wgt,
                           float* __restrict__ out,
                           const float* __restrict__ mask,
                           int Din, int Hin, int Win,
                           int Dout, int Hout, int Wout, int pad)
{
    constexpr int CCH = (CIN % 32 == 0) ? 32 : CIN;
    const int tid = threadIdx.x;
    const int nout = Dout * Hout * Wout;
    const int base = blockIdx.x * NS;

    __shared__ int sz[NS], sy[NS], sx[NS];
    __shared__ float xs[NS][CCH + 1];

    if (tid < NS) {
        int o = base + tid;
        if (o < nout) {
            int xw = o % Wout, yy = (o / Wout) % Hout, zz = o / (Wout * Hout);
            sz[tid] = zz * STRIDE - pad;
            sy[tid] = yy * STRIDE - pad;
            sx[tid] = xw * STRIDE - pad;
        } else {
            sz[tid] = -100000; sy[tid] = 0; sx[tid] = 0;
        }
    }
    __syncthreads();

    float acc[NS];
#pragma unroll
    for (int s = 0; s < NS; s++) acc[s] = 0.f;

    for (int tap = 0; tap < K * K * K; tap++) {
        const int dz = tap / (K * K), dy = (tap / K) % K, dx = tap % K;
        for (int ci0 = 0; ci0 < CIN; ci0 += CCH) {
            for (int e = tid; e < NS * CCH; e += COUT) {
                int s = e / CCH, ci = e - s * CCH;
                int iz = sz[s] + dz, iy = sy[s] + dy, ix = sx[s] + dx;
                float v = 0.f;
                if ((unsigned)iz < (unsigned)Din && (unsigned)iy < (unsigned)Hin &&
                    (unsigned)ix < (unsigned)Win)
                    v = in[(size_t)((iz * Hin + iy) * Win + ix) * CIN + ci0 + ci];
                xs[s][ci] = v;
            }
            __syncthreads();
            const float* wp = wgt + (size_t)(tap * CIN + ci0) * COUT + tid;
#pragma unroll 4
            for (int ci = 0; ci < CCH; ci++) {
                float wv = __ldg(wp + (size_t)ci * COUT);
#pragma unroll
                for (int s = 0; s < NS; s++) acc[s] += xs[s][ci] * wv;
            }
            __syncthreads();
        }
    }

#pragma unroll
    for (int s = 0; s < NS; s++) {
        int o = base + s;
        if (o < nout) {
            float mv = mask ? mask[o] : 1.f;
            out[(size_t)o * COUT + tid] = acc[s] * mv;
        }
    }
}

// ---------------------------------------------------------------------------
// Mask pool: reduce_window(max) with init 0
// ---------------------------------------------------------------------------
__global__ void mask_pool_kernel(const float* __restrict__ m, float* __restrict__ mo,
                                 int Din, int Hin, int Win,
                                 int Dout, int Hout, int Wout,
                                 int k, int s, int pad)
{
    int o = blockIdx.x * blockDim.x + threadIdx.x;
    int nout = Dout * Hout * Wout;
    if (o >= nout) return;
    int xw = o % Wout, y = (o / Wout) % Hout, z = o / (Wout * Hout);
    float r = 0.f;
    for (int dz = 0; dz < k; dz++)
        for (int dy = 0; dy < k; dy++)
            for (int dx = 0; dx < k; dx++) {
                int iz = z * s - pad + dz, iy = y * s - pad + dy, ix = xw * s - pad + dx;
                if ((unsigned)iz < (unsigned)Din && (unsigned)iy < (unsigned)Hin &&
                    (unsigned)ix < (unsigned)Win)
                    r = fmaxf(r, m[(iz * Hin + iy) * Win + ix]);
            }
    mo[o] = r;
}

// ---------------------------------------------------------------------------
// Masked max pool 2x2x2 stride 2 VALID. Writes pooled x and pooled mask.
// blockDim.x == C, gridDim.x == nout.
// ---------------------------------------------------------------------------
template <int C>
__global__ void maxpool_kernel(const float* __restrict__ x, const float* __restrict__ m,
                               float* __restrict__ xo, float* __restrict__ mo,
                               int Hin, int Win, int Hout, int Wout)
{
    int o = blockIdx.x;
    int c = threadIdx.x;
    int xw = o % Wout, y = (o / Wout) % Hout, z = o / (Wout * Hout);
    float best = -FLT_MAX, mn = 0.f;
    for (int dz = 0; dz < 2; dz++)
        for (int dy = 0; dy < 2; dy++)
            for (int dx = 0; dx < 2; dx++) {
                int v = ((2 * z + dz) * Hin + (2 * y + dy)) * Win + (2 * xw + dx);
                float mv = m[v];
                mn = fmaxf(mn, mv);
                float xv = x[(size_t)v * C + c];
                best = fmaxf(best, mv > 0.f ? xv : -FLT_MAX);
            }
    xo[(size_t)o * C + c] = (mn > 0.f) ? best : 0.f;
    if (c == 0) mo[o] = mn;
}

// ---------------------------------------------------------------------------
// conv_transpose k=2 s=2 VALID (JAX transpose_kernel=False):
//   out[z,y,x,co] = sum_ci in[z/2,y/2,x/2,ci] * w[1-z%2, 1-y%2, 1-x%2, ci, co]
// then multiplied by mask. blockDim.x == COUT, gridDim.x == nout.
// ---------------------------------------------------------------------------
template <int CIN, int COUT>
__global__ void deconv_kernel(const float* __restrict__ in,
                              const float* __restrict__ wgt,
                              float* __restrict__ out,
                              const float* __restrict__ mask,
                              int Hout, int Wout)
{
    int o = blockIdx.x;
    int c = threadIdx.x;
    int xw = o % Wout, y = (o / Wout) % Hout, z = o / (Wout * Hout);
    int Hin = Hout / 2, Win = Wout / 2;
    int iv = ((z / 2) * Hin + (y / 2)) * Win + (xw / 2);
    int tap = ((1 - (z & 1)) * 2 + (1 - (y & 1))) * 2 + (1 - (xw & 1));
    const float* wp = wgt + (size_t)tap * CIN * COUT + c;
    const float* ip = in + (size_t)iv * CIN;
    float acc = 0.f;
#pragma unroll 4
    for (int ci = 0; ci < CIN; ci++)
        acc += ip[ci] * __ldg(wp + (size_t)ci * COUT);
    out[(size_t)o * COUT + c] = acc * mask[o];
}

// ---------------------------------------------------------------------------
// Host launcher
// ---------------------------------------------------------------------------
extern "C" void kernel_launch(void* const* d_in, const int* in_sizes, int n_in,
                              void* d_out, int out_size)
{
    const float* feats = (const float*)d_in[0];
    const int*   coors = (const int*)d_in[1];
    const float* w[19];
    for (int i = 1; i <= 18; i++) w[i] = (const float*)d_in[2 + i];
    float* out = (float*)d_out;
    const int N = in_sizes[0] / 3;

    float *A, *B, *m0, *m1, *m2, *m3, *m4, *m5;
    cudaGetSymbolAddress((void**)&A,  g_bufA);
    cudaGetSymbolAddress((void**)&B,  g_bufB);
    cudaGetSymbolAddress((void**)&m0, g_m0);
    cudaGetSymbolAddress((void**)&m1, g_m1);
    cudaGetSymbolAddress((void**)&m2, g_m2);
    cudaGetSymbolAddress((void**)&m3, g_m3);
    cudaGetSymbolAddress((void**)&m4, g_m4);
    cudaGetSymbolAddress((void**)&m5, g_m5);

    const int nv0 = 128 * 128 * 32;   // 524288
    const int nv1 = 64 * 64 * 16;     // 65536
    const int nv2 = 32 * 32 * 8;      // 8192
    const int nv3 = 16 * 16 * 4;      // 1024
    const int nv4 = 8 * 8 * 2;        // 128
    const int nv5 = 4 * 4 * 1;        // 16

    // ---- scatter: x0 (bufA, 3ch) + m0 ----
    cudaMemsetAsync(m0, 0, (size_t)nv0 * 4, 0);
    cudaMemsetAsync(A,  0, (size_t)nv0 * 3 * 4, 0);
    scatter_kernel<<<(N + 255) / 256, 256>>>(feats, coors, N, A, m0);

    const int gsub = (N + 31) / 32;
    // ---- w1: subm 3->32, A->B ----
    cudaMemsetAsync(B, 0, (size_t)nv0 * 32 * 4, 0);
    conv_subm<3, 32, 32><<<gsub, 32>>>(A, w[1], B, coors, N, 128, 128, 32);
    // ---- w2: subm 32->32, B->A ----
    cudaMemsetAsync(A, 0, (size_t)nv0 * 32 * 4, 0);
    conv_subm<32, 32, 32><<<gsub, 32>>>(B, w[2], A, coors, N, 128, 128, 32);
    // ---- w3: subm 32->64, A->B ----
    cudaMemsetAsync(B, 0, (size_t)nv0 * 64 * 4, 0);
    conv_subm<32, 64, 32><<<gsub, 64>>>(A, w[3], B, coors, N, 128, 128, 32);
    // ---- w4: subm 64->64, B->A ----
    cudaMemsetAsync(A, 0, (size_t)nv0 * 64 * 4, 0);
    conv_subm<64, 64, 32><<<gsub, 64>>>(B, w[4], A, coors, N, 128, 128, 32);

    // ---- m1 = mask_pool(m0, 3, 2, pad 1) ----
    mask_pool_kernel<<<(nv1 + 255) / 256, 256>>>(m0, m1, 128, 128, 32, 64, 64, 16, 3, 2, 1);
    // ---- w5: conv 64->64 k3 s2 pad1, A->B, *m1 ----
    conv_dense<64, 64, 3, 2, 32><<<nv1 / 32, 64>>>(A, w[5], B, m1, 128, 128, 32, 64, 64, 16, 1);
    // ---- w6: subm(dense) 64->96, B->A, *m1 ----
    conv_dense<64, 96, 3, 1, 32><<<nv1 / 32, 96>>>(B, w[6], A, m1, 64, 64, 16, 64, 64, 16, 1);
    // ---- w7: 96->96, A->B, *m1 ----
    conv_dense<96, 96, 3, 1, 32><<<nv1 / 32, 96>>>(A, w[7], B, m1, 64, 64, 16, 64, 64, 16, 1);

    // ---- m2 = mask_pool(m1, 2, 2, VALID) ----
    mask_pool_kernel<<<(nv2 + 255) / 256, 256>>>(m1, m2, 64, 64, 16, 32, 32, 8, 2, 2, 0);
    // ---- w8: conv 96->96 k2 s2 VALID, B->A, *m2 ----
    conv_dense<96, 96, 2, 2, 32><<<nv2 / 32, 96>>>(B, w[8], A, m2, 64, 64, 16, 32, 32, 8, 0);
    // ---- w9: 96->128, A->B, *m2 ----
    conv_dense<96, 128, 3, 1, 16><<<nv2 / 16, 128>>>(A, w[9], B, m2, 32, 32, 8, 32, 32, 8, 1);
    // ---- w10: 128->128, B->A, *m2 ----
    conv_dense<128, 128, 3, 1, 16><<<nv2 / 16, 128>>>(B, w[10], A, m2, 32, 32, 8, 32, 32, 8, 1);

    // ---- maxpool S2->S3 : (A, m2) -> (B, m3) ----
    maxpool_kernel<128><<<nv3, 128>>>(A, m2, B, m3, 32, 8, 16, 4);
    // ---- w11: 128->160, B->A, *m3 ----
    conv_dense<128, 160, 3, 1, 8><<<nv3 / 8, 160>>>(B, w[11], A, m3, 16, 16, 4, 16, 16, 4, 1);
    // ---- w12: 160->160, A->B, *m3 ----
    conv_dense<160, 160, 3, 1, 8><<<nv3 / 8, 160>>>(A, w[12], B, m3, 16, 16, 4, 16, 16, 4, 1);

    // ---- maxpool S3->S4 : (B, m3) -> (A, m4) ----
    maxpool_kernel<160><<<nv4, 160>>>(B, m3, A, m4, 16, 4, 8, 2);
    // ---- w13: 160->192, A->B, *m4 ----
    conv_dense<160, 192, 3, 1, 1><<<nv4, 192>>>(A, w[13], B, m4, 8, 8, 2, 8, 8, 2, 1);
    // ---- w14: 192->192, B->A, *m4 ----
    conv_dense<192, 192, 3, 1, 1><<<nv4, 192>>>(B, w[14], A, m4, 8, 8, 2, 8, 8, 2, 1);

    // ---- maxpool S4->S5 : (A, m4) -> (B, m5) ----
    maxpool_kernel<192><<<nv5, 192>>>(A, m4, B, m5, 8, 2, 4, 1);
    // ---- w15: 192->224, B->A, *m5 ----
    conv_dense<192, 224, 3, 1, 1><<<nv5, 224>>>(B, w[15], A, m5, 4, 4, 1, 4, 4, 1, 1);
    // ---- w16: 224->224, A->B, *m5 ----
    conv_dense<224, 224, 3, 1, 1><<<nv5, 224>>>(A, w[16], B, m5, 4, 4, 1, 4, 4, 1, 1);

    // ---- deconv w17: 224->128, S5 -> S4, *m4 : B->A ----
    deconv_kernel<224, 128><<<nv4, 128>>>(B, w[17], A, m4, 8, 2);
    // ---- deconv w18: 128->64, S4 -> S3, *m3 : A -> d_out ----
    deconv_kernel<128, 64><<<nv3, 64>>>(A, w[18], out, m3, 16, 4);

    (void)n_in; (void)out_size; (void)m5;
}

// round 9
// speedup vs baseline: 1.4333x; 1.0001x over previous
#include <cuda_runtime.h>
#include <cfloat>
#include <cstdint>

// ---------------------------------------------------------------------------
// Static scratch (no cudaMalloc allowed). Two ping-pong buffers sized for the
// largest tensor: 128*128*32 voxels * 64 ch = 33,554,432 floats (128 MiB each).
// ---------------------------------------------------------------------------
__device__ float g_bufA[33554432];
__device__ float g_bufB[33554432];
__device__ float g_m0[524288];   // 128*128*32
__device__ float g_m1[65536];    // 64*64*16
__device__ float g_m2[8192];     // 32*32*8
__device__ float g_m3[1024];     // 16*16*4
__device__ float g_m4[128];      // 8*8*2
__device__ float g_m5[16];       // 4*4*1

// ---------------------------------------------------------------------------
// Scatter points into dense grid (grid is pre-zeroed with memset)
// ---------------------------------------------------------------------------
__global__ void scatter_kernel(const float* __restrict__ feats,
                               const int* __restrict__ coors, int n,
                               float* __restrict__ x0, float* __restrict__ m0)
{
    int i = blockIdx.x * blockDim.x + threadIdx.x;
    if (i >= n) return;
    int z = coors[i * 4 + 1], y = coors[i * 4 + 2], xw = coors[i * 4 + 3];
    int v = (z * 128 + y) * 32 + xw;
    m0[v] = 1.0f;
    x0[v * 3 + 0] = feats[i * 3 + 0];
    x0[v * 3 + 1] = feats[i * 3 + 1];
    x0[v * 3 + 2] = feats[i * 3 + 2];
}

// ---------------------------------------------------------------------------
// Submanifold conv at full resolution: compute ONLY at the N active sites
// taken from the coors list (3x3x3, stride 1, pad 1). Output buffer must be
// zeroed beforehand so inactive voxels read 0 in the next layer.
// blockDim.x == COUT. Each block handles NS sites.
// ---------------------------------------------------------------------------
template <int CIN, int COUT, int NS>
__global__ void conv_subm(const float* __restrict__ in,
                          const float* __restrict__ wgt,
                          float* __restrict__ out,
                          const int* __restrict__ coors, int nsites,
                          int D, int H, int W)
{
    constexpr int CCH = (CIN % 32 == 0) ? 32 : CIN;
    const int tid = threadIdx.x;
    const int base = blockIdx.x * NS;

    __shared__ int sz[NS], sy[NS], sx[NS];
    __shared__ float xs[NS][CCH + 1];

    if (tid < NS) {
        int i = base + tid;
        if (i < nsites) {
            sz[tid] = coors[i * 4 + 1] - 1;
            sy[tid] = coors[i * 4 + 2] - 1;
            sx[tid] = coors[i * 4 + 3] - 1;
        } else {
            sz[tid] = -100000; sy[tid] = 0; sx[tid] = 0;
        }
    }
    __syncthreads();

    float acc[NS];
#pragma unroll
    for (int s = 0; s < NS; s++) acc[s] = 0.f;

    for (int tap = 0; tap < 27; tap++) {
        const int dz = tap / 9, dy = (tap / 3) % 3, dx = tap % 3;
        for (int ci0 = 0; ci0 < CIN; ci0 += CCH) {
            for (int e = tid; e < NS * CCH; e += COUT) {
                int s = e / CCH, ci = e - s * CCH;
                int iz = sz[s] + dz, iy = sy[s] + dy, ix = sx[s] + dx;
                float v = 0.f;
                if ((unsigned)iz < (unsigned)D && (unsigned)iy < (unsigned)H &&
                    (unsigned)ix < (unsigned)W)
                    v = in[(size_t)((iz * H + iy) * W + ix) * CIN + ci0 + ci];
                xs[s][ci] = v;
            }
            __syncthreads();
            const float* wp = wgt + (size_t)(tap * CIN + ci0) * COUT + tid;
#pragma unroll 4
            for (int ci = 0; ci < CCH; ci++) {
                float wv = __ldg(wp + (size_t)ci * COUT);
#pragma unroll
                for (int s = 0; s < NS; s++) acc[s] += xs[s][ci] * wv;
            }
            __syncthreads();
        }
    }

#pragma unroll
    for (int s = 0; s < NS; s++) {
        int i = base + s;
        if (i < nsites) {
            int v = ((sz[s] + 1) * H + (sy[s] + 1)) * W + (sx[s] + 1);
            out[(size_t)v * COUT + tid] = acc[s];
        }
    }
}

// ---------------------------------------------------------------------------
// Dense 3D conv, optional mask epilogue (out *= mask[o]).
// blockDim.x == COUT. Each block handles NS output sites.
// ---------------------------------------------------------------------------
template <int CIN, int COUT, int K, int STRIDE, int NS>
__global__ void conv_dense(const float* __restrict__ in,
                           const float* __restrict__ wgt,
                           float* __restrict__ out,
                           const float* __restrict__ mask,
                           int Din, int Hin, int Win,
                           int Dout, int Hout, int Wout, int pad)
{
    constexpr int CCH = (CIN % 32 == 0) ? 32 : CIN;
    const int tid = threadIdx.x;
    const int nout = Dout * Hout * Wout;
    const int base = blockIdx.x * NS;

    __shared__ int sz[NS], sy[NS], sx[NS];
    __shared__ float xs[NS][CCH + 1];

    if (tid < NS) {
        int o = base + tid;
        if (o < nout) {
            int xw = o % Wout, yy = (o / Wout) % Hout, zz = o / (Wout * Hout);
            sz[tid] = zz * STRIDE - pad;
            sy[tid] = yy * STRIDE - pad;
            sx[tid] = xw * STRIDE - pad;
        } else {
            sz[tid] = -100000; sy[tid] = 0; sx[tid] = 0;
        }
    }
    __syncthreads();

    float acc[NS];
#pragma unroll
    for (int s = 0; s < NS; s++) acc[s] = 0.f;

    for (int tap = 0; tap < K * K * K; tap++) {
        const int dz = tap / (K * K), dy = (tap / K) % K, dx = tap % K;
        for (int ci0 = 0; ci0 < CIN; ci0 += CCH) {
            for (int e = tid; e < NS * CCH; e += COUT) {
                int s = e / CCH, ci = e - s * CCH;
                int iz = sz[s] + dz, iy = sy[s] + dy, ix = sx[s] + dx;
                float v = 0.f;
                if ((unsigned)iz < (unsigned)Din && (unsigned)iy < (unsigned)Hin &&
                    (unsigned)ix < (unsigned)Win)
                    v = in[(size_t)((iz * Hin + iy) * Win + ix) * CIN + ci0 + ci];
                xs[s][ci] = v;
            }
            __syncthreads();
            const float* wp = wgt + (size_t)(tap * CIN + ci0) * COUT + tid;
#pragma unroll 4
            for (int ci = 0; ci < CCH; ci++) {
                float wv = __ldg(wp + (size_t)ci * COUT);
#pragma unroll
                for (int s = 0; s < NS; s++) acc[s] += xs[s][ci] * wv;
            }
            __syncthreads();
        }
    }

#pragma unroll
    for (int s = 0; s < NS; s++) {
        int o = base + s;
        if (o < nout) {
            float mv = mask ? mask[o] : 1.f;
            out[(size_t)o * COUT + tid] = acc[s] * mv;
        }
    }
}

// ---------------------------------------------------------------------------
// Mask pool: reduce_window(max) with init 0
// ---------------------------------------------------------------------------
__global__ void mask_pool_kernel(const float* __restrict__ m, float* __restrict__ mo,
                                 int Din, int Hin, int Win,
                                 int Dout, int Hout, int Wout,
                                 int k, int s, int pad)
{
    int o = blockIdx.x * blockDim.x + threadIdx.x;
    int nout = Dout * Hout * Wout;
    if (o >= nout) return;
    int xw = o % Wout, y = (o / Wout) % Hout, z = o / (Wout * Hout);
    float r = 0.f;
    for (int dz = 0; dz < k; dz++)
        for (int dy = 0; dy < k; dy++)
            for (int dx = 0; dx < k; dx++) {
                int iz = z * s - pad + dz, iy = y * s - pad + dy, ix = xw * s - pad + dx;
                if ((unsigned)iz < (unsigned)Din && (unsigned)iy < (unsigned)Hin &&
                    (unsigned)ix < (unsigned)Win)
                    r = fmaxf(r, m[(iz * Hin + iy) * Win + ix]);
            }
    mo[o] = r;
}

// ---------------------------------------------------------------------------
// Masked max pool 2x2x2 stride 2 VALID. Writes pooled x and pooled mask.
// blockDim.x == C, gridDim.x == nout.
// ---------------------------------------------------------------------------
template <int C>
__global__ void maxpool_kernel(const float* __restrict__ x, const float* __restrict__ m,
                               float* __restrict__ xo, float* __restrict__ mo,
                               int Hin, int Win, int Hout, int Wout)
{
    int o = blockIdx.x;
    int c = threadIdx.x;
    int xw = o % Wout, y = (o / Wout) % Hout, z = o / (Wout * Hout);
    float best = -FLT_MAX, mn = 0.f;
    for (int dz = 0; dz < 2; dz++)
        for (int dy = 0; dy < 2; dy++)
            for (int dx = 0; dx < 2; dx++) {
                int v = ((2 * z + dz) * Hin + (2 * y + dy)) * Win + (2 * xw + dx);
                float mv = m[v];
                mn = fmaxf(mn, mv);
                float xv = x[(size_t)v * C + c];
                best = fmaxf(best, mv > 0.f ? xv : -FLT_MAX);
            }
    xo[(size_t)o * C + c] = (mn > 0.f) ? best : 0.f;
    if (c == 0) mo[o] = mn;
}

// ---------------------------------------------------------------------------
// conv_transpose k=2 s=2 VALID (JAX transpose_kernel=False):
//   out[z,y,x,co] = sum_ci in[z/2,y/2,x/2,ci] * w[1-z%2, 1-y%2, 1-x%2, ci, co]
// then multiplied by mask. blockDim.x == COUT, gridDim.x == nout.
// ---------------------------------------------------------------------------
template <int CIN, int COUT>
__global__ void deconv_kernel(const float* __restrict__ in,
                              const float* __restrict__ wgt,
                              float* __restrict__ out,
                              const float* __restrict__ mask,
                              int Hout, int Wout)
{
    int o = blockIdx.x;
    int c = threadIdx.x;
    int xw = o % Wout, y = (o / Wout) % Hout, z = o / (Wout * Hout);
    int Hin = Hout / 2, Win = Wout / 2;
    int iv = ((z / 2) * Hin + (y / 2)) * Win + (xw / 2);
    int tap = ((1 - (z & 1)) * 2 + (1 - (y & 1))) * 2 + (1 - (xw & 1));
    const float* wp = wgt + (size_t)tap * CIN * COUT + c;
    const float* ip = in + (size_t)iv * CIN;
    float acc = 0.f;
#pragma unroll 4
    for (int ci = 0; ci < CIN; ci++)
        acc += ip[ci] * __ldg(wp + (size_t)ci * COUT);
    out[(size_t)o * COUT + c] = acc * mask[o];
}

// ---------------------------------------------------------------------------
// Host launcher
// ---------------------------------------------------------------------------
extern "C" void kernel_launch(void* const* d_in, const int* in_sizes, int n_in,
                              void* d_out, int out_size)
{
    const float* feats = (const float*)d_in[0];
    const int*   coors = (const int*)d_in[1];
    const float* w[19];
    for (int i = 1; i <= 18; i++) w[i] = (const float*)d_in[2 + i];
    float* out = (float*)d_out;
    const int N = in_sizes[0] / 3;

    float *A, *B, *m0, *m1, *m2, *m3, *m4, *m5;
    cudaGetSymbolAddress((void**)&A,  g_bufA);
    cudaGetSymbolAddress((void**)&B,  g_bufB);
    cudaGetSymbolAddress((void**)&m0, g_m0);
    cudaGetSymbolAddress((void**)&m1, g_m1);
    cudaGetSymbolAddress((void**)&m2, g_m2);
    cudaGetSymbolAddress((void**)&m3, g_m3);
    cudaGetSymbolAddress((void**)&m4, g_m4);
    cudaGetSymbolAddress((void**)&m5, g_m5);

    const int nv0 = 128 * 128 * 32;   // 524288
    const int nv1 = 64 * 64 * 16;     // 65536
    const int nv2 = 32 * 32 * 8;      // 8192
    const int nv3 = 16 * 16 * 4;      // 1024
    const int nv4 = 8 * 8 * 2;        // 128
    const int nv5 = 4 * 4 * 1;        // 16

    // ---- scatter: x0 (bufA, 3ch) + m0 ----
    cudaMemsetAsync(m0, 0, (size_t)nv0 * 4, 0);
    cudaMemsetAsync(A,  0, (size_t)nv0 * 3 * 4, 0);
    scatter_kernel<<<(N + 255) / 256, 256>>>(feats, coors, N, A, m0);

    const int gsub = (N + 31) / 32;
    // ---- w1: subm 3->32, A->B ----
    cudaMemsetAsync(B, 0, (size_t)nv0 * 32 * 4, 0);
    conv_subm<3, 32, 32><<<gsub, 32>>>(A, w[1], B, coors, N, 128, 128, 32);
    // ---- w2: subm 32->32, B->A ----
    cudaMemsetAsync(A, 0, (size_t)nv0 * 32 * 4, 0);
    conv_subm<32, 32, 32><<<gsub, 32>>>(B, w[2], A, coors, N, 128, 128, 32);
    // ---- w3: subm 32->64, A->B ----
    cudaMemsetAsync(B, 0, (size_t)nv0 * 64 * 4, 0);
    conv_subm<32, 64, 32><<<gsub, 64>>>(A, w[3], B, coors, N, 128, 128, 32);
    // ---- w4: subm 64->64, B->A ----
    cudaMemsetAsync(A, 0, (size_t)nv0 * 64 * 4, 0);
    conv_subm<64, 64, 32><<<gsub, 64>>>(B, w[4], A, coors, N, 128, 128, 32);

    // ---- m1 = mask_pool(m0, 3, 2, pad 1) ----
    mask_pool_kernel<<<(nv1 + 255) / 256, 256>>>(m0, m1, 128, 128, 32, 64, 64, 16, 3, 2, 1);
    // ---- w5: conv 64->64 k3 s2 pad1, A->B, *m1 ----
    conv_dense<64, 64, 3, 2, 32><<<nv1 / 32, 64>>>(A, w[5], B, m1, 128, 128, 32, 64, 64, 16, 1);
    // ---- w6: subm(dense) 64->96, B->A, *m1 ----
    conv_dense<64, 96, 3, 1, 32><<<nv1 / 32, 96>>>(B, w[6], A, m1, 64, 64, 16, 64, 64, 16, 1);
    // ---- w7: 96->96, A->B, *m1 ----
    conv_dense<96, 96, 3, 1, 32><<<nv1 / 32, 96>>>(A, w[7], B, m1, 64, 64, 16, 64, 64, 16, 1);

    // ---- m2 = mask_pool(m1, 2, 2, VALID) ----
    mask_pool_kernel<<<(nv2 + 255) / 256, 256>>>(m1, m2, 64, 64, 16, 32, 32, 8, 2, 2, 0);
    // ---- w8: conv 96->96 k2 s2 VALID, B->A, *m2 ----
    conv_dense<96, 96, 2, 2, 32><<<nv2 / 32, 96>>>(B, w[8], A, m2, 64, 64, 16, 32, 32, 8, 0);
    // ---- w9: 96->128, A->B, *m2 ----
    conv_dense<96, 128, 3, 1, 16><<<nv2 / 16, 128>>>(A, w[9], B, m2, 32, 32, 8, 32, 32, 8, 1);
    // ---- w10: 128->128, B->A, *m2 ----
    conv_dense<128, 128, 3, 1, 16><<<nv2 / 16, 128>>>(B, w[10], A, m2, 32, 32, 8, 32, 32, 8, 1);

    // ---- maxpool S2->S3 : (A, m2) -> (B, m3) ----
    maxpool_kernel<128><<<nv3, 128>>>(A, m2, B, m3, 32, 8, 16, 4);
    // ---- w11: 128->160, B->A, *m3 ----
    conv_dense<128, 160, 3, 1, 8><<<nv3 / 8, 160>>>(B, w[11], A, m3, 16, 16, 4, 16, 16, 4, 1);
    // ---- w12: 160->160, A->B, *m3 ----
    conv_dense<160, 160, 3, 1, 8><<<nv3 / 8, 160>>>(A, w[12], B, m3, 16, 16, 4, 16, 16, 4, 1);

    // ---- maxpool S3->S4 : (B, m3) -> (A, m4) ----
    maxpool_kernel<160><<<nv4, 160>>>(B, m3, A, m4, 16, 4, 8, 2);
    // ---- w13: 160->192, A->B, *m4 ----
    conv_dense<160, 192, 3, 1, 1><<<nv4, 192>>>(A, w[13], B, m4, 8, 8, 2, 8, 8, 2, 1);
    // ---- w14: 192->192, B->A, *m4 ----
    conv_dense<192, 192, 3, 1, 1><<<nv4, 192>>>(B, w[14], A, m4, 8, 8, 2, 8, 8, 2, 1);

    // ---- maxpool S4->S5 : (A, m4) -> (B, m5) ----
    maxpool_kernel<192><<<nv5, 192>>>(A, m4, B, m5, 8, 2, 4, 1);
    // ---- w15: 192->224, B->A, *m5 ----
    conv_dense<192, 224, 3, 1, 1><<<nv5, 224>>>(B, w[15], A, m5, 4, 4, 1, 4, 4, 1, 1);
    // ---- w16: 224->224, A->B, *m5 ----
    conv_dense<224, 224, 3, 1, 1><<<nv5, 224>>>(A, w[16], B, m5, 4, 4, 1, 4, 4, 1, 1);

    // ---- deconv w17: 224->128, S5 -> S4, *m4 : B->A ----
    deconv_kernel<224, 128><<<nv4, 128>>>(B, w[17], A, m4, 8, 2);
    // ---- deconv w18: 128->64, S4 -> S3, *m3 : A -> d_out ----
    deconv_kernel<128, 64><<<nv3, 64>>>(A, w[18], out, m3, 16, 4);

    (void)n_in; (void)out_size; (void)m5;
}